// round 16
// baseline (speedup 1.0000x reference)
#include <cuda_runtime.h>
#include <cuda_fp16.h>
#include <cstdint>

// Problem constants
#define NN 100000
#define EE 1600000
#define HID 128
#define NCLS 40
#define GG 1563             // gemm blocks = ceil(NN/64)
#define HG 782              // head blocks = ceil(NN/128)
#define PAD 128             // bucket slots per destination node
#define WCONVB 16           // W-convert blocks
#define FILLB 6250          // fill blocks (EE/256)
#define ZB 391              // cursor-zero blocks appended to k_head
#define SCALEB 6250         // scale-pass blocks (NN*HID/8/256)

// ---------------- mma.sync / cp.async helpers ----------------
__device__ __forceinline__ void ldsm_x4(uint32_t addr, uint32_t& r0, uint32_t& r1,
                                        uint32_t& r2, uint32_t& r3) {
    asm volatile("ldmatrix.sync.aligned.m8n8.x4.shared.b16 {%0,%1,%2,%3}, [%4];"
                 : "=r"(r0), "=r"(r1), "=r"(r2), "=r"(r3) : "r"(addr));
}
__device__ __forceinline__ void ldsm_x4_t(uint32_t addr, uint32_t& r0, uint32_t& r1,
                                          uint32_t& r2, uint32_t& r3) {
    asm volatile("ldmatrix.sync.aligned.m8n8.x4.trans.shared.b16 {%0,%1,%2,%3}, [%4];"
                 : "=r"(r0), "=r"(r1), "=r"(r2), "=r"(r3) : "r"(addr));
}
__device__ __forceinline__ void mma16816(float c[4], const uint32_t a[4],
                                         uint32_t b0, uint32_t b1) {
    asm volatile(
        "mma.sync.aligned.m16n8k16.row.col.f32.f16.f16.f32 "
        "{%0,%1,%2,%3}, {%4,%5,%6,%7}, {%8,%9}, {%0,%1,%2,%3};"
        : "+f"(c[0]), "+f"(c[1]), "+f"(c[2]), "+f"(c[3])
        : "r"(a[0]), "r"(a[1]), "r"(a[2]), "r"(a[3]), "r"(b0), "r"(b1));
}
__device__ __forceinline__ void cpa16(uint32_t d, const void* s, bool p) {
    asm volatile("cp.async.cg.shared.global [%0], [%1], 16, %2;"
                 :: "r"(d), "l"(s), "r"(p ? 16 : 0));
}
__device__ __forceinline__ void cpcommit() { asm volatile("cp.async.commit_group;"); }

// ---------------- device scratch (static; no cudaMalloc allowed) ----------------
__device__ __half g_w1h[HID * HID];
__device__ __half g_w2h[HID * HID];
__device__ __half g_tmp[(size_t)NN * HID];  // fp16 messages
__device__ __half g_h1h[(size_t)NN * HID];  // layer-1 hidden, fp16
__device__ int    g_cursor[NN];             // in-degree (excl self loop); ZERO at entry
__device__ int    g_colp[(size_t)NN * PAD]; // padded buckets: sources per dst

// ---------------- K0: W1/W2 fp16 converts (tiny) ----------------
__global__ void k_wconv(const float* __restrict__ W1, const float* __restrict__ W2) {
    int i = blockIdx.x * blockDim.x + threadIdx.x;   // 0..4095 = HID*HID/4
    float4 v = ((const float4*)W1)[i];
    half2 a = __floats2half2_rn(v.x, v.y), b = __floats2half2_rn(v.z, v.w);
    uint2 p; p.x = *(unsigned*)&a; p.y = *(unsigned*)&b;
    ((uint2*)g_w1h)[i] = p;
    float4 w = ((const float4*)W2)[i];
    half2 c = __floats2half2_rn(w.x, w.y), d = __floats2half2_rn(w.z, w.w);
    uint2 q; q.x = *(unsigned*)&c; q.y = *(unsigned*)&d;
    ((uint2*)g_w2h)[i] = q;
}

// ---------------- shared GEMM pieces (BM=64, BN=128, BK=32) ----------------
#define ABUF (64 * 40 * 2)
#define WBUF (32 * 136 * 2)

struct GemmCtx {
    uint32_t as_base, ws_base;
    int a_row, a_col, b_krow, b_ncol, wm, wn, m0;
};

__device__ __forceinline__ void gemm_setup(GemmCtx& c, int bid, void* As, void* Ws) {
    int t = threadIdx.x, lane = t & 31, wid = t >> 5;
    c.m0 = bid * 64;
    c.wm = (wid & 3) * 16;
    c.wn = (wid >> 2) * 64;
    c.as_base = (uint32_t)__cvta_generic_to_shared(As);
    c.ws_base = (uint32_t)__cvta_generic_to_shared(Ws);
    c.a_row = c.wm + (lane & 15);
    c.a_col = (lane >> 4) * 8;
    int g = lane >> 3;
    c.b_krow = (lane & 7) + (g >> 1) * 8;
    c.b_ncol = c.wn + (g & 1) * 8;
}

__device__ __forceinline__ void gemm_mma_chunk(const GemmCtx& c, int buf,
                                               float acc[8][4]) {
    uint32_t a_b = c.as_base + buf * ABUF;
    uint32_t w_b = c.ws_base + buf * WBUF;
    #pragma unroll
    for (int ks = 0; ks < 32; ks += 16) {
        uint32_t a[4];
        ldsm_x4(a_b + (c.a_row * 40 + ks + c.a_col) * 2, a[0], a[1], a[2], a[3]);
        uint32_t b[8][2];
        #pragma unroll
        for (int ntq = 0; ntq < 4; ntq++) {
            uint32_t addr = w_b + ((ks + c.b_krow) * 136 + c.b_ncol + ntq * 16) * 2;
            uint32_t r0, r1, r2, r3;
            ldsm_x4_t(addr, r0, r1, r2, r3);
            b[ntq * 2][0] = r0; b[ntq * 2 + 1][0] = r1;
            b[ntq * 2][1] = r2; b[ntq * 2 + 1][1] = r3;
        }
        #pragma unroll
        for (int nt = 0; nt < 8; nt++)
            mma16816(acc[nt], a, b[nt][0], b[nt][1]);
    }
}

__device__ __forceinline__ void stage_w(uint32_t ws_base, int buf,
                                        const __half* Wm, int kc) {
    int t = threadIdx.x;
    #pragma unroll
    for (int j = 0; j < 2; j++) {
        int i = t + j * 256;          // 0..511
        int row = i >> 4, c16 = i & 15;
        cpa16(ws_base + buf * WBUF + row * 272 + c16 * 16,
              Wm + (size_t)(kc + row) * HID + c16 * 8, true);
    }
}

// epilogue variant A: RAW store (no scaling)
__device__ __forceinline__ void gemm_epilogue_raw(const GemmCtx& c, float acc[8][4]) {
    int lane = threadIdx.x & 31;
    int qr = lane >> 2, qc = (lane & 3) * 2;
    int row_lo = c.m0 + c.wm + qr;
    int row_hi = row_lo + 8;
    #pragma unroll
    for (int nt = 0; nt < 8; nt++) {
        int colg = c.wn + nt * 8 + qc;
        if (row_lo < NN) {
            half2 h = __floats2half2_rn(acc[nt][0], acc[nt][1]);
            *(half2*)(g_tmp + (size_t)row_lo * HID + colg) = h;
        }
        if (row_hi < NN) {
            half2 h = __floats2half2_rn(acc[nt][2], acc[nt][3]);
            *(half2*)(g_tmp + (size_t)row_hi * HID + colg) = h;
        }
    }
}

// epilogue variant B: prescale by rsqrt(deg) (layer 2 — cursor is final by then)
__device__ __forceinline__ void gemm_epilogue_scaled(const GemmCtx& c, float acc[8][4]) {
    int lane = threadIdx.x & 31;
    int qr = lane >> 2, qc = (lane & 3) * 2;
    int row_lo = c.m0 + c.wm + qr;
    int row_hi = row_lo + 8;
    float sc_lo = (row_lo < NN) ? rsqrtf((float)g_cursor[row_lo] + 1.0f) : 0.f;
    float sc_hi = (row_hi < NN) ? rsqrtf((float)g_cursor[row_hi] + 1.0f) : 0.f;
    #pragma unroll
    for (int nt = 0; nt < 8; nt++) {
        int colg = c.wn + nt * 8 + qc;
        if (row_lo < NN) {
            half2 h = __floats2half2_rn(acc[nt][0] * sc_lo, acc[nt][1] * sc_lo);
            *(half2*)(g_tmp + (size_t)row_lo * HID + colg) = h;
        }
        if (row_hi < NN) {
            half2 h = __floats2half2_rn(acc[nt][2] * sc_hi, acc[nt][3] * sc_hi);
            *(half2*)(g_tmp + (size_t)row_hi * HID + colg) = h;
        }
    }
}

// ---------------- K1: GEMM1 (raw, fp32 x inline-convert) || bucket fill ----------------
__global__ void __launch_bounds__(256, 3)
k_mega1(const float* __restrict__ x, const void* __restrict__ ei) {
    __shared__ __align__(16) __half As[2][64][40];
    __shared__ __align__(16) __half Ws[2][32][136];
    if (blockIdx.x >= GG) {
        // -------- bucket fill (independent of GEMM; counts degrees) --------
        __shared__ int sfmt;
        if (threadIdx.x == 0) {
            const int* w = (const int*)ei;
            int is64 = 1;
            #pragma unroll
            for (int j = 1; j < 64; j += 2) is64 &= (w[j] == 0);
            sfmt = is64;
        }
        __syncthreads();
        int e = (blockIdx.x - GG) * 256 + threadIdx.x;
        if (e < EE) {
            const int* w = (const int*)ei;
            int s, d;
            if (sfmt) { s = w[(size_t)e * 2]; d = w[((size_t)EE + e) * 2]; }
            else      { s = w[e];             d = w[(size_t)EE + e]; }
            if ((unsigned)d < NN) {
                int pos = atomicAdd(&g_cursor[d], 1);
                int c = ((unsigned)s < NN) ? s : d;
                if (pos < PAD) g_colp[(size_t)d * PAD + pos] = c;
            }
        }
        return;
    }
    // -------- GEMM layer 1, raw output --------
    GemmCtx c;
    gemm_setup(c, blockIdx.x, &As[0][0][0], &Ws[0][0][0]);
    int t = threadIdx.x;

    float acc[8][4];
    #pragma unroll
    for (int nt = 0; nt < 8; nt++)
        #pragma unroll
        for (int q = 0; q < 4; q++) acc[nt][q] = 0.f;

    int srow = t >> 2, scol = (t & 3) * 8;
    int sgrow = c.m0 + srow;
    bool sp = sgrow < NN;
    const float* aSrc = x + (size_t)sgrow * HID + scol;

    float4 c0 = make_float4(0,0,0,0), c1 = c0;
    if (sp) { c0 = *(const float4*)aSrc; c1 = *(const float4*)(aSrc + 4); }
    stage_w(c.ws_base, 0, g_w1h, 0);
    cpcommit();

    #pragma unroll
    for (int i = 0; i < 4; i++) {
        float4 n0 = make_float4(0,0,0,0), n1 = n0;
        if (i < 3) {
            int kc = (i + 1) * 32;
            if (sp) { n0 = *(const float4*)(aSrc + kc); n1 = *(const float4*)(aSrc + kc + 4); }
            stage_w(c.ws_base, (i + 1) & 1, g_w1h, kc);
            cpcommit();
        }
        {
            half2 h0 = __floats2half2_rn(c0.x, c0.y), h1 = __floats2half2_rn(c0.z, c0.w);
            half2 h2 = __floats2half2_rn(c1.x, c1.y), h3 = __floats2half2_rn(c1.z, c1.w);
            uint4 p;
            p.x = *(unsigned*)&h0; p.y = *(unsigned*)&h1;
            p.z = *(unsigned*)&h2; p.w = *(unsigned*)&h3;
            *(uint4*)((char*)As + (i & 1) * ABUF + srow * 80 + scol * 2) = p;
        }
        if (i < 3) asm volatile("cp.async.wait_group 1;" ::: "memory");
        else       asm volatile("cp.async.wait_group 0;" ::: "memory");
        __syncthreads();
        gemm_mma_chunk(c, i & 1, acc);
        __syncthreads();
        c0 = n0; c1 = n1;
    }
    gemm_epilogue_raw(c, acc);
}

// ---------------- K2: scale pass — g_tmp[row] *= rsqrt(deg[row]) ----------------
__global__ void k_scale() {
    int i = blockIdx.x * blockDim.x + threadIdx.x;   // 0 .. NN*HID/8
    int row = i >> 4, seg = i & 15;
    float dv = rsqrtf((float)g_cursor[row] + 1.0f);
    uint4 p = *(uint4*)(g_tmp + (size_t)row * HID + seg * 8);
    unsigned r[4] = {p.x, p.y, p.z, p.w};
    #pragma unroll
    for (int q = 0; q < 4; q++) {
        float2 f = __half22float2(*(half2*)&r[q]);
        half2 h = __floats2half2_rn(f.x * dv, f.y * dv);
        r[q] = *(unsigned*)&h;
    }
    p.x = r[0]; p.y = r[1]; p.z = r[2]; p.w = r[3];
    *(uint4*)(g_tmp + (size_t)row * HID + seg * 8) = p;
}

// ---------------- K4: GEMM layer 2 (fp16 g_h1h, prescaled epilogue) ----------------
__global__ void __launch_bounds__(256, 3)
k_gemm2() {
    __shared__ __align__(16) __half As[2][64][40];
    __shared__ __align__(16) __half Ws[2][32][136];
    GemmCtx c;
    gemm_setup(c, blockIdx.x, &As[0][0][0], &Ws[0][0][0]);
    int t = threadIdx.x;

    float acc[8][4];
    #pragma unroll
    for (int nt = 0; nt < 8; nt++)
        #pragma unroll
        for (int q = 0; q < 4; q++) acc[nt][q] = 0.f;

    int srow = t >> 2, sseg = t & 3;
    int sgrow = c.m0 + srow;
    bool sp = sgrow < NN;
    const __half* aSrc = g_h1h + (size_t)sgrow * HID + sseg * 8;
    uint32_t aDst = c.as_base + srow * 80 + sseg * 16;

    cpa16(aDst, aSrc, sp);
    stage_w(c.ws_base, 0, g_w2h, 0);
    cpcommit();

    #pragma unroll
    for (int i = 0; i < 4; i++) {
        if (i < 3) {
            int buf = (i + 1) & 1, kc = (i + 1) * 32;
            cpa16(aDst + buf * ABUF, aSrc + kc, sp);
            stage_w(c.ws_base, buf, g_w2h, kc);
            cpcommit();
            asm volatile("cp.async.wait_group 1;" ::: "memory");
        } else {
            asm volatile("cp.async.wait_group 0;" ::: "memory");
        }
        __syncthreads();
        gemm_mma_chunk(c, i & 1, acc);
        __syncthreads();
    }
    gemm_epilogue_scaled(c, acc);
}

// ---------------- SpMM: out[d] = relu(dinv[d] * Σ msg_scaled + b) ----------------
// DST=0: write fp16 g_h1h. DST=1: write fp32 outp (h2).
template<int DST>
__global__ void k_spmm(const float* __restrict__ bias, float* __restrict__ outp) {
    int gw = (blockIdx.x * blockDim.x + threadIdx.x) >> 5;
    int lane = threadIdx.x & 31;
    if (gw >= NN) return;
    int cnt0 = g_cursor[gw];
    float dv = rsqrtf((float)cnt0 + 1.0f);
    int cnt = (cnt0 > PAD) ? PAD : cnt0;
    const int* cols = g_colp + (size_t)gw * PAD;
    const __half* tmp = (const __half*)g_tmp;

    float4 acc;
    {   // self-loop message (already scaled by dinv[gw])
        uint2 u = *(const uint2*)(tmp + (size_t)gw * HID + lane * 4);
        float2 a = __half22float2(*(half2*)&u.x), b = __half22float2(*(half2*)&u.y);
        acc = make_float4(a.x, a.y, b.x, b.y);
    }
    int j = 0;
    for (; j + 4 <= cnt; j += 4) {
        int s0 = cols[j], s1 = cols[j + 1], s2 = cols[j + 2], s3 = cols[j + 3];
        uint2 u0 = *(const uint2*)(tmp + (size_t)s0 * HID + lane * 4);
        uint2 u1 = *(const uint2*)(tmp + (size_t)s1 * HID + lane * 4);
        uint2 u2 = *(const uint2*)(tmp + (size_t)s2 * HID + lane * 4);
        uint2 u3 = *(const uint2*)(tmp + (size_t)s3 * HID + lane * 4);
        float2 a0 = __half22float2(*(half2*)&u0.x), b0 = __half22float2(*(half2*)&u0.y);
        float2 a1 = __half22float2(*(half2*)&u1.x), b1 = __half22float2(*(half2*)&u1.y);
        float2 a2 = __half22float2(*(half2*)&u2.x), b2 = __half22float2(*(half2*)&u2.y);
        float2 a3 = __half22float2(*(half2*)&u3.x), b3 = __half22float2(*(half2*)&u3.y);
        acc.x += a0.x + a1.x + a2.x + a3.x;
        acc.y += a0.y + a1.y + a2.y + a3.y;
        acc.z += b0.x + b1.x + b2.x + b3.x;
        acc.w += b0.y + b1.y + b2.y + b3.y;
    }
    for (; j < cnt; j++) {
        int s = cols[j];
        uint2 u = *(const uint2*)(tmp + (size_t)s * HID + lane * 4);
        float2 a = __half22float2(*(half2*)&u.x), b = __half22float2(*(half2*)&u.y);
        acc.x += a.x; acc.y += a.y; acc.z += b.x; acc.w += b.y;
    }

    float4 b4 = *(const float4*)(bias + lane * 4);
    float4 o;
    o.x = fmaxf(fmaf(acc.x, dv, b4.x), 0.f);
    o.y = fmaxf(fmaf(acc.y, dv, b4.y), 0.f);
    o.z = fmaxf(fmaf(acc.z, dv, b4.z), 0.f);
    o.w = fmaxf(fmaf(acc.w, dv, b4.w), 0.f);

    if (DST == 0) {
        half2 ha = __floats2half2_rn(o.x, o.y);
        half2 hb = __floats2half2_rn(o.z, o.w);
        uint2 pk;
        pk.x = *(unsigned*)&ha; pk.y = *(unsigned*)&hb;
        *(uint2*)(g_h1h + (size_t)gw * HID + lane * 4) = pk;
    } else {
        *(float4*)(outp + (size_t)gw * HID + lane * 4) = o;
    }
}

// ---------------- head GEMM (HMMA, fp32 h2 source) + cursor-reset blocks ----------
__global__ void __launch_bounds__(256)
k_head(const float* __restrict__ H2, const float* __restrict__ Wh,
       const float* __restrict__ bh, float* __restrict__ S) {
    __shared__ __align__(16) __half As[128][72];
    __shared__ __align__(16) __half Wsh[128][56];
    if (blockIdx.x >= HG) {   // cursor reset for next graph replay
        int i = (blockIdx.x - HG) * 256 + threadIdx.x;
        if (i < NN) g_cursor[i] = 0;
        return;
    }
    int t = threadIdx.x, lane = t & 31, wid = t >> 5;
    int m0 = blockIdx.x * 128;
    int wm = wid * 16;

    for (int i = t; i < 128 * 24; i += 256) {
        int r = i / 24, c2 = (i % 24) * 2;
        float lo = (c2 < NCLS) ? Wh[(size_t)r * NCLS + c2] : 0.f;
        float hi = (c2 + 1 < NCLS) ? Wh[(size_t)r * NCLS + c2 + 1] : 0.f;
        *(half2*)&Wsh[r][c2] = __floats2half2_rn(lo, hi);
    }

    float acc[6][4];
    #pragma unroll
    for (int nt = 0; nt < 6; nt++)
        #pragma unroll
        for (int q = 0; q < 4; q++) acc[nt][q] = 0.f;

    uint32_t as_base = (uint32_t)__cvta_generic_to_shared(&As[0][0]);
    uint32_t ws_base = (uint32_t)__cvta_generic_to_shared(&Wsh[0][0]);
    int a_row = wm + (lane & 15);
    int a_col = (lane >> 4) * 8;
    int g = lane >> 3;
    int b_krow = (lane & 7) + (g >> 1) * 8;
    int b_ncol = (g & 1) * 8;

    #pragma unroll
    for (int kc = 0; kc < HID; kc += 64) {
        {   // stage fp32 h2 chunk [128][64] with inline convert
            int r = t >> 1, cs = (t & 1) * 32;
            int grow = m0 + r;
            const float* src = H2 + (size_t)grow * HID + kc + cs;
            #pragma unroll
            for (int q = 0; q < 4; q++) {
                float4 v0 = make_float4(0,0,0,0), v1 = v0;
                if (grow < NN) {
                    v0 = *(const float4*)(src + q * 8);
                    v1 = *(const float4*)(src + q * 8 + 4);
                }
                half2 h0 = __floats2half2_rn(v0.x, v0.y), h1 = __floats2half2_rn(v0.z, v0.w);
                half2 h2 = __floats2half2_rn(v1.x, v1.y), h3 = __floats2half2_rn(v1.z, v1.w);
                uint4 p;
                p.x = *(unsigned*)&h0; p.y = *(unsigned*)&h1;
                p.z = *(unsigned*)&h2; p.w = *(unsigned*)&h3;
                *(uint4*)&As[r][cs + q * 8] = p;
            }
        }
        __syncthreads();

        #pragma unroll
        for (int ks = 0; ks < 64; ks += 16) {
            uint32_t a[4];
            ldsm_x4(as_base + (a_row * 72 + ks + a_col) * 2, a[0], a[1], a[2], a[3]);
            uint32_t b[6][2];
            #pragma unroll
            for (int ntq = 0; ntq < 3; ntq++) {
                uint32_t addr = ws_base + ((kc + ks + b_krow) * 56 + b_ncol + ntq * 16) * 2;
                uint32_t r0, r1, r2, r3;
                ldsm_x4_t(addr, r0, r1, r2, r3);
                b[ntq * 2][0] = r0; b[ntq * 2 + 1][0] = r1;
                b[ntq * 2][1] = r2; b[ntq * 2 + 1][1] = r3;
            }
            #pragma unroll
            for (int nt = 0; nt < 6; nt++)
                mma16816(acc[nt], a, b[nt][0], b[nt][1]);
        }
        __syncthreads();
    }

    int qr = lane >> 2, qc = (lane & 3) * 2;
    int row_lo = m0 + wm + qr, row_hi = row_lo + 8;
    #pragma unroll
    for (int nt = 0; nt < 5; nt++) {
        int col = nt * 8 + qc;
        float blo = bh[col], bhi = bh[col + 1];
        if (row_lo < NN) {
            S[(size_t)row_lo * NCLS + col]     = acc[nt][0] + blo;
            S[(size_t)row_lo * NCLS + col + 1] = acc[nt][1] + bhi;
        }
        if (row_hi < NN) {
            S[(size_t)row_hi * NCLS + col]     = acc[nt][2] + blo;
            S[(size_t)row_hi * NCLS + col + 1] = acc[nt][3] + bhi;
        }
    }
}

// ---------------- launch ----------------
extern "C" void kernel_launch(void* const* d_in, const int* in_sizes, int n_in,
                              void* d_out, int out_size) {
    const float* x   = (const float*)d_in[0];
    const void*  ei  = d_in[1];                 // int32 or int64, detected per fill block
    const float* W1  = (const float*)d_in[2];
    const float* b1  = (const float*)d_in[3];
    const float* W2  = (const float*)d_in[4];
    const float* b2  = (const float*)d_in[5];
    const float* Wh  = (const float*)d_in[6];
    const float* bh  = (const float*)d_in[7];

    float* out = (float*)d_out;
    float* scores = out;                       // [NN, 40]
    float* h2 = out + (size_t)NN * NCLS;       // [NN, 128]

    const int TB = 256;
    int spmm_grid = (NN * 32 + TB - 1) / TB;

    k_wconv<<<WCONVB, TB>>>(W1, W2);
    k_mega1<<<GG + FILLB, TB>>>(x, ei);        // GEMM1(raw) || bucket fill
    k_scale<<<SCALEB, TB>>>();                 // apply dinv[row] to g_tmp
    k_spmm<0><<<spmm_grid, TB>>>(b1, nullptr);
    k_gemm2<<<GG, TB>>>();
    k_spmm<1><<<spmm_grid, TB>>>(b2, h2);
    k_head<<<HG + ZB, TB>>>(h2, Wh, bh, scores);   // head + cursor reset
}

// round 17
// speedup vs baseline: 1.0133x; 1.0133x over previous
#include <cuda_runtime.h>
#include <cuda_fp16.h>
#include <cstdint>

// Problem constants
#define NN 100000
#define EE 1600000
#define HID 128
#define NCLS 40
#define GG 1563             // gemm blocks = ceil(NN/64)
#define HG 782              // head blocks = ceil(NN/128)
#define PAD 128             // bucket slots per destination node
#define WCONVB 16           // W-convert blocks in k_init
#define FILLB 6250          // fill blocks in k_init (EE/256)
#define ZB 391              // cursor-zero blocks appended to k_head

// ---------------- mma.sync / cp.async helpers ----------------
__device__ __forceinline__ void ldsm_x4(uint32_t addr, uint32_t& r0, uint32_t& r1,
                                        uint32_t& r2, uint32_t& r3) {
    asm volatile("ldmatrix.sync.aligned.m8n8.x4.shared.b16 {%0,%1,%2,%3}, [%4];"
                 : "=r"(r0), "=r"(r1), "=r"(r2), "=r"(r3) : "r"(addr));
}
__device__ __forceinline__ void ldsm_x4_t(uint32_t addr, uint32_t& r0, uint32_t& r1,
                                          uint32_t& r2, uint32_t& r3) {
    asm volatile("ldmatrix.sync.aligned.m8n8.x4.trans.shared.b16 {%0,%1,%2,%3}, [%4];"
                 : "=r"(r0), "=r"(r1), "=r"(r2), "=r"(r3) : "r"(addr));
}
__device__ __forceinline__ void mma16816(float c[4], const uint32_t a[4],
                                         uint32_t b0, uint32_t b1) {
    asm volatile(
        "mma.sync.aligned.m16n8k16.row.col.f32.f16.f16.f32 "
        "{%0,%1,%2,%3}, {%4,%5,%6,%7}, {%8,%9}, {%0,%1,%2,%3};"
        : "+f"(c[0]), "+f"(c[1]), "+f"(c[2]), "+f"(c[3])
        : "r"(a[0]), "r"(a[1]), "r"(a[2]), "r"(a[3]), "r"(b0), "r"(b1));
}
__device__ __forceinline__ void cpa16(uint32_t d, const void* s, bool p) {
    asm volatile("cp.async.cg.shared.global [%0], [%1], 16, %2;"
                 :: "r"(d), "l"(s), "r"(p ? 16 : 0));
}
__device__ __forceinline__ void cpcommit() { asm volatile("cp.async.commit_group;"); }

// ---------------- device scratch (static; no cudaMalloc allowed) ----------------
__device__ __half g_w1h[HID * HID];
__device__ __half g_w2h[HID * HID];
__device__ __half g_tmp[(size_t)NN * HID];  // fp16 messages, pre-scaled by dinv[src]
__device__ __half g_h1h[(size_t)NN * HID];  // layer-1 hidden, fp16
__device__ int    g_cursor[NN];             // in-degree (excl self loop); ZERO at entry
__device__ int    g_colp[(size_t)NN * PAD]; // padded buckets: sources per dst

// ---------------- K0: W fp16 converts || bucket fill ----------------
__global__ void __launch_bounds__(256)
k_init(const float* __restrict__ W1, const float* __restrict__ W2,
       const void* __restrict__ ei) {
    if (blockIdx.x < WCONVB) {
        int i = blockIdx.x * blockDim.x + threadIdx.x;   // 0..4095 = HID*HID/4
        float4 v = ((const float4*)W1)[i];
        half2 a = __floats2half2_rn(v.x, v.y), b = __floats2half2_rn(v.z, v.w);
        uint2 p; p.x = *(unsigned*)&a; p.y = *(unsigned*)&b;
        ((uint2*)g_w1h)[i] = p;
        float4 w = ((const float4*)W2)[i];
        half2 c = __floats2half2_rn(w.x, w.y), d = __floats2half2_rn(w.z, w.w);
        uint2 q; q.x = *(unsigned*)&c; q.y = *(unsigned*)&d;
        ((uint2*)g_w2h)[i] = q;
    } else {
        __shared__ int sfmt;
        if (threadIdx.x == 0) {
            const int* w = (const int*)ei;
            int is64 = 1;
            #pragma unroll
            for (int j = 1; j < 64; j += 2) is64 &= (w[j] == 0);
            sfmt = is64;
        }
        __syncthreads();
        int e = (blockIdx.x - WCONVB) * 256 + threadIdx.x;
        if (e < EE) {
            const int* w = (const int*)ei;
            int s, d;
            if (sfmt) { s = w[(size_t)e * 2]; d = w[((size_t)EE + e) * 2]; }
            else      { s = w[e];             d = w[(size_t)EE + e]; }
            if ((unsigned)d < NN) {
                int pos = atomicAdd(&g_cursor[d], 1);
                int c = ((unsigned)s < NN) ? s : d;
                if (pos < PAD) g_colp[(size_t)d * PAD + pos] = c;
            }
        }
    }
}

// ---------------- shared GEMM mainloop pieces (BM=64, BN=128, BK=32) ----------------
#define ABUF (64 * 40 * 2)
#define WBUF (32 * 136 * 2)

struct GemmCtx {
    uint32_t as_base, ws_base;
    int a_row, a_col, b_krow, b_ncol, wm, wn, m0;
};

__device__ __forceinline__ void gemm_setup(GemmCtx& c, int bid, void* As, void* Ws) {
    int t = threadIdx.x, lane = t & 31, wid = t >> 5;
    c.m0 = bid * 64;
    c.wm = (wid & 3) * 16;
    c.wn = (wid >> 2) * 64;
    c.as_base = (uint32_t)__cvta_generic_to_shared(As);
    c.ws_base = (uint32_t)__cvta_generic_to_shared(Ws);
    c.a_row = c.wm + (lane & 15);
    c.a_col = (lane >> 4) * 8;
    int g = lane >> 3;
    c.b_krow = (lane & 7) + (g >> 1) * 8;
    c.b_ncol = c.wn + (g & 1) * 8;
}

__device__ __forceinline__ void gemm_mma_chunk(const GemmCtx& c, int buf,
                                               float acc[8][4]) {
    uint32_t a_b = c.as_base + buf * ABUF;
    uint32_t w_b = c.ws_base + buf * WBUF;
    #pragma unroll
    for (int ks = 0; ks < 32; ks += 16) {
        uint32_t a[4];
        ldsm_x4(a_b + (c.a_row * 40 + ks + c.a_col) * 2, a[0], a[1], a[2], a[3]);
        uint32_t b[8][2];
        #pragma unroll
        for (int ntq = 0; ntq < 4; ntq++) {
            uint32_t addr = w_b + ((ks + c.b_krow) * 136 + c.b_ncol + ntq * 16) * 2;
            uint32_t r0, r1, r2, r3;
            ldsm_x4_t(addr, r0, r1, r2, r3);
            b[ntq * 2][0] = r0; b[ntq * 2 + 1][0] = r1;
            b[ntq * 2][1] = r2; b[ntq * 2 + 1][1] = r3;
        }
        #pragma unroll
        for (int nt = 0; nt < 8; nt++)
            mma16816(acc[nt], a, b[nt][0], b[nt][1]);
    }
}

__device__ __forceinline__ void stage_w(uint32_t ws_base, int buf,
                                        const __half* Wm, int kc) {
    int t = threadIdx.x;
    #pragma unroll
    for (int j = 0; j < 2; j++) {
        int i = t + j * 256;          // 0..511
        int row = i >> 4, c16 = i & 15;
        cpa16(ws_base + buf * WBUF + row * 272 + c16 * 16,
              Wm + (size_t)(kc + row) * HID + c16 * 8, true);
    }
}

// epilogue: scale by rsqrt(deg), fp16 store to g_tmp
__device__ __forceinline__ void gemm_epilogue(const GemmCtx& c, float acc[8][4]) {
    int lane = threadIdx.x & 31;
    int qr = lane >> 2, qc = (lane & 3) * 2;
    int row_lo = c.m0 + c.wm + qr;
    int row_hi = row_lo + 8;
    float sc_lo = (row_lo < NN) ? rsqrtf((float)g_cursor[row_lo] + 1.0f) : 0.f;
    float sc_hi = (row_hi < NN) ? rsqrtf((float)g_cursor[row_hi] + 1.0f) : 0.f;
    #pragma unroll
    for (int nt = 0; nt < 8; nt++) {
        int colg = c.wn + nt * 8 + qc;
        if (row_lo < NN) {
            half2 h = __floats2half2_rn(acc[nt][0] * sc_lo, acc[nt][1] * sc_lo);
            *(half2*)(g_tmp + (size_t)row_lo * HID + colg) = h;
        }
        if (row_hi < NN) {
            half2 h = __floats2half2_rn(acc[nt][2] * sc_hi, acc[nt][3] * sc_hi);
            *(half2*)(g_tmp + (size_t)row_hi * HID + colg) = h;
        }
    }
}

// ---------------- K1: GEMM layer 1, fp32 x source with inline convert ----------------
__global__ void __launch_bounds__(256, 3)
k_gemm1(const float* __restrict__ x) {
    __shared__ __align__(16) __half As[2][64][40];
    __shared__ __align__(16) __half Ws[2][32][136];
    GemmCtx c;
    gemm_setup(c, blockIdx.x, &As[0][0][0], &Ws[0][0][0]);
    int t = threadIdx.x;

    float acc[8][4];
    #pragma unroll
    for (int nt = 0; nt < 8; nt++)
        #pragma unroll
        for (int q = 0; q < 4; q++) acc[nt][q] = 0.f;

    int srow = t >> 2, scol = (t & 3) * 8;
    int sgrow = c.m0 + srow;
    bool sp = sgrow < NN;
    const float* aSrc = x + (size_t)sgrow * HID + scol;

    float4 c0 = make_float4(0,0,0,0), c1 = c0;
    if (sp) { c0 = *(const float4*)aSrc; c1 = *(const float4*)(aSrc + 4); }
    stage_w(c.ws_base, 0, g_w1h, 0);
    cpcommit();

    #pragma unroll
    for (int i = 0; i < 4; i++) {
        float4 n0 = make_float4(0,0,0,0), n1 = n0;
        if (i < 3) {
            int kc = (i + 1) * 32;
            if (sp) { n0 = *(const float4*)(aSrc + kc); n1 = *(const float4*)(aSrc + kc + 4); }
            stage_w(c.ws_base, (i + 1) & 1, g_w1h, kc);
            cpcommit();
        }
        {
            half2 h0 = __floats2half2_rn(c0.x, c0.y), h1 = __floats2half2_rn(c0.z, c0.w);
            half2 h2 = __floats2half2_rn(c1.x, c1.y), h3 = __floats2half2_rn(c1.z, c1.w);
            uint4 p;
            p.x = *(unsigned*)&h0; p.y = *(unsigned*)&h1;
            p.z = *(unsigned*)&h2; p.w = *(unsigned*)&h3;
            *(uint4*)((char*)As + (i & 1) * ABUF + srow * 80 + scol * 2) = p;
        }
        if (i < 3) asm volatile("cp.async.wait_group 1;" ::: "memory");
        else       asm volatile("cp.async.wait_group 0;" ::: "memory");
        __syncthreads();
        gemm_mma_chunk(c, i & 1, acc);
        __syncthreads();
        c0 = n0; c1 = n1;
    }
    gemm_epilogue(c, acc);
}

// ---------------- K3: GEMM layer 2, fp16 g_h1h source (all cp.async) ----------------
__global__ void __launch_bounds__(256, 3)
k_gemm2() {
    __shared__ __align__(16) __half As[2][64][40];
    __shared__ __align__(16) __half Ws[2][32][136];
    GemmCtx c;
    gemm_setup(c, blockIdx.x, &As[0][0][0], &Ws[0][0][0]);
    int t = threadIdx.x;

    float acc[8][4];
    #pragma unroll
    for (int nt = 0; nt < 8; nt++)
        #pragma unroll
        for (int q = 0; q < 4; q++) acc[nt][q] = 0.f;

    int srow = t >> 2, sseg = t & 3;
    int sgrow = c.m0 + srow;
    bool sp = sgrow < NN;
    const __half* aSrc = g_h1h + (size_t)sgrow * HID + sseg * 8;
    uint32_t aDst = c.as_base + srow * 80 + sseg * 16;

    cpa16(aDst, aSrc, sp);
    stage_w(c.ws_base, 0, g_w2h, 0);
    cpcommit();

    #pragma unroll
    for (int i = 0; i < 4; i++) {
        if (i < 3) {
            int buf = (i + 1) & 1, kc = (i + 1) * 32;
            cpa16(aDst + buf * ABUF, aSrc + kc, sp);
            stage_w(c.ws_base, buf, g_w2h, kc);
            cpcommit();
            asm volatile("cp.async.wait_group 1;" ::: "memory");
        } else {
            asm volatile("cp.async.wait_group 0;" ::: "memory");
        }
        __syncthreads();
        gemm_mma_chunk(c, i & 1, acc);
        __syncthreads();
    }
    gemm_epilogue(c, acc);
}

// ---------------- SpMM: out[d] = relu(dinv[d] * Σ msg_scaled + b) ----------------
// fp16 pairwise-tree accumulation per 4-edge group (6 HADD2 + 1 cvt pair),
// fp32 master accumulator. 32-bit byte addressing into g_tmp.
// DST=0: write fp16 g_h1h. DST=1: write fp32 outp (h2).
template<int DST>
__global__ void k_spmm(const float* __restrict__ bias, float* __restrict__ outp) {
    int gw = (blockIdx.x * blockDim.x + threadIdx.x) >> 5;
    int lane = threadIdx.x & 31;
    if (gw >= NN) return;
    int cnt0 = g_cursor[gw];
    float dv = rsqrtf((float)cnt0 + 1.0f);
    int cnt = (cnt0 > PAD) ? PAD : cnt0;
    const int* cols = g_colp + (size_t)gw * PAD;
    const char* base = (const char*)g_tmp;
    unsigned loff = lane * 8u;      // 8 bytes = 4 halves per lane

    float4 acc;
    {   // self-loop message (already scaled by dinv[gw])
        uint2 u = *(const uint2*)(base + ((unsigned)gw << 8) + loff);
        float2 a = __half22float2(*(half2*)&u.x), b = __half22float2(*(half2*)&u.y);
        acc = make_float4(a.x, a.y, b.x, b.y);
    }
    int j = 0;
    for (; j + 4 <= cnt; j += 4) {
        unsigned o0 = (unsigned)cols[j]     << 8;
        unsigned o1 = (unsigned)cols[j + 1] << 8;
        unsigned o2 = (unsigned)cols[j + 2] << 8;
        unsigned o3 = (unsigned)cols[j + 3] << 8;
        uint2 u0 = *(const uint2*)(base + o0 + loff);
        uint2 u1 = *(const uint2*)(base + o1 + loff);
        uint2 u2 = *(const uint2*)(base + o2 + loff);
        uint2 u3 = *(const uint2*)(base + o3 + loff);
        // fp16 pairwise tree: ((m0+m1)+(m2+m3)) per half2 slot
        half2 pa = __hadd2(*(half2*)&u0.x, *(half2*)&u1.x);
        half2 pb = __hadd2(*(half2*)&u2.x, *(half2*)&u3.x);
        half2 qa = __hadd2(*(half2*)&u0.y, *(half2*)&u1.y);
        half2 qb = __hadd2(*(half2*)&u2.y, *(half2*)&u3.y);
        half2 sa = __hadd2(pa, pb);
        half2 sb = __hadd2(qa, qb);
        float2 fa = __half22float2(sa), fb = __half22float2(sb);
        acc.x += fa.x; acc.y += fa.y; acc.z += fb.x; acc.w += fb.y;
    }
    for (; j < cnt; j++) {
        unsigned o = (unsigned)cols[j] << 8;
        uint2 u = *(const uint2*)(base + o + loff);
        float2 a = __half22float2(*(half2*)&u.x), b = __half22float2(*(half2*)&u.y);
        acc.x += a.x; acc.y += a.y; acc.z += b.x; acc.w += b.y;
    }

    float4 b4 = *(const float4*)(bias + lane * 4);
    float4 o;
    o.x = fmaxf(fmaf(acc.x, dv, b4.x), 0.f);
    o.y = fmaxf(fmaf(acc.y, dv, b4.y), 0.f);
    o.z = fmaxf(fmaf(acc.z, dv, b4.z), 0.f);
    o.w = fmaxf(fmaf(acc.w, dv, b4.w), 0.f);

    if (DST == 0) {
        half2 ha = __floats2half2_rn(o.x, o.y);
        half2 hb = __floats2half2_rn(o.z, o.w);
        uint2 pk;
        pk.x = *(unsigned*)&ha; pk.y = *(unsigned*)&hb;
        *(uint2*)(g_h1h + (size_t)gw * HID + lane * 4) = pk;
    } else {
        *(float4*)(outp + (size_t)gw * HID + lane * 4) = o;
    }
}

// ---------------- head GEMM (HMMA, fp32 h2 source) + cursor-reset blocks ----------
__global__ void __launch_bounds__(256)
k_head(const float* __restrict__ H2, const float* __restrict__ Wh,
       const float* __restrict__ bh, float* __restrict__ S) {
    __shared__ __align__(16) __half As[128][72];
    __shared__ __align__(16) __half Wsh[128][56];
    if (blockIdx.x >= HG) {   // cursor reset for next graph replay
        int i = (blockIdx.x - HG) * 256 + threadIdx.x;
        if (i < NN) g_cursor[i] = 0;
        return;
    }
    int t = threadIdx.x, lane = t & 31, wid = t >> 5;
    int m0 = blockIdx.x * 128;
    int wm = wid * 16;

    for (int i = t; i < 128 * 24; i += 256) {
        int r = i / 24, c2 = (i % 24) * 2;
        float lo = (c2 < NCLS) ? Wh[(size_t)r * NCLS + c2] : 0.f;
        float hi = (c2 + 1 < NCLS) ? Wh[(size_t)r * NCLS + c2 + 1] : 0.f;
        *(half2*)&Wsh[r][c2] = __floats2half2_rn(lo, hi);
    }

    float acc[6][4];
    #pragma unroll
    for (int nt = 0; nt < 6; nt++)
        #pragma unroll
        for (int q = 0; q < 4; q++) acc[nt][q] = 0.f;

    uint32_t as_base = (uint32_t)__cvta_generic_to_shared(&As[0][0]);
    uint32_t ws_base = (uint32_t)__cvta_generic_to_shared(&Wsh[0][0]);
    int a_row = wm + (lane & 15);
    int a_col = (lane >> 4) * 8;
    int g = lane >> 3;
    int b_krow = (lane & 7) + (g >> 1) * 8;
    int b_ncol = (g & 1) * 8;

    #pragma unroll
    for (int kc = 0; kc < HID; kc += 64) {
        {   // stage fp32 h2 chunk [128][64] with inline convert
            int r = t >> 1, cs = (t & 1) * 32;
            int grow = m0 + r;
            const float* src = H2 + (size_t)grow * HID + kc + cs;
            #pragma unroll
            for (int q = 0; q < 4; q++) {
                float4 v0 = make_float4(0,0,0,0), v1 = v0;
                if (grow < NN) {
                    v0 = *(const float4*)(src + q * 8);
                    v1 = *(const float4*)(src + q * 8 + 4);
                }
                half2 h0 = __floats2half2_rn(v0.x, v0.y), h1 = __floats2half2_rn(v0.z, v0.w);
                half2 h2 = __floats2half2_rn(v1.x, v1.y), h3 = __floats2half2_rn(v1.z, v1.w);
                uint4 p;
                p.x = *(unsigned*)&h0; p.y = *(unsigned*)&h1;
                p.z = *(unsigned*)&h2; p.w = *(unsigned*)&h3;
                *(uint4*)&As[r][cs + q * 8] = p;
            }
        }
        __syncthreads();

        #pragma unroll
        for (int ks = 0; ks < 64; ks += 16) {
            uint32_t a[4];
            ldsm_x4(as_base + (a_row * 72 + ks + a_col) * 2, a[0], a[1], a[2], a[3]);
            uint32_t b[6][2];
            #pragma unroll
            for (int ntq = 0; ntq < 3; ntq++) {
                uint32_t addr = ws_base + ((kc + ks + b_krow) * 56 + b_ncol + ntq * 16) * 2;
                uint32_t r0, r1, r2, r3;
                ldsm_x4_t(addr, r0, r1, r2, r3);
                b[ntq * 2][0] = r0; b[ntq * 2 + 1][0] = r1;
                b[ntq * 2][1] = r2; b[ntq * 2 + 1][1] = r3;
            }
            #pragma unroll
            for (int nt = 0; nt < 6; nt++)
                mma16816(acc[nt], a, b[nt][0], b[nt][1]);
        }
        __syncthreads();
    }

    int qr = lane >> 2, qc = (lane & 3) * 2;
    int row_lo = m0 + wm + qr, row_hi = row_lo + 8;
    #pragma unroll
    for (int nt = 0; nt < 5; nt++) {
        int col = nt * 8 + qc;
        float blo = bh[col], bhi = bh[col + 1];
        if (row_lo < NN) {
            S[(size_t)row_lo * NCLS + col]     = acc[nt][0] + blo;
            S[(size_t)row_lo * NCLS + col + 1] = acc[nt][1] + bhi;
        }
        if (row_hi < NN) {
            S[(size_t)row_hi * NCLS + col]     = acc[nt][2] + blo;
            S[(size_t)row_hi * NCLS + col + 1] = acc[nt][3] + bhi;
        }
    }
}

// ---------------- launch ----------------
extern "C" void kernel_launch(void* const* d_in, const int* in_sizes, int n_in,
                              void* d_out, int out_size) {
    const float* x   = (const float*)d_in[0];
    const void*  ei  = d_in[1];                 // int32 or int64, detected per fill block
    const float* W1  = (const float*)d_in[2];
    const float* b1  = (const float*)d_in[3];
    const float* W2  = (const float*)d_in[4];
    const float* b2  = (const float*)d_in[5];
    const float* Wh  = (const float*)d_in[6];
    const float* bh  = (const float*)d_in[7];

    float* out = (float*)d_out;
    float* scores = out;                       // [NN, 40]
    float* h2 = out + (size_t)NN * NCLS;       // [NN, 128]

    const int TB = 256;
    int spmm_grid = (NN * 32 + TB - 1) / TB;

    k_init<<<WCONVB + FILLB, TB>>>(W1, W2, ei);   // W converts || bucket fill
    k_gemm1<<<GG, TB>>>(x);
    k_spmm<0><<<spmm_grid, TB>>>(b1, nullptr);
    k_gemm2<<<GG, TB>>>();
    k_spmm<1><<<spmm_grid, TB>>>(b2, h2);
    k_head<<<HG + ZB, TB>>>(h2, Wh, bh, scores);  // head + cursor reset
}